// round 1
// baseline (speedup 1.0000x reference)
#include <cuda_runtime.h>

#define T_DIM 256
#define B_DIM 128
#define DIN 20
#define H_DIM 1024
#define OUT_DIM 1095
#define L_DIM 3

// Scratch (device globals — no allocation allowed in kernel_launch)
__device__ float g_h[(size_t)T_DIM * B_DIM * H_DIM];        // 134 MB
__device__ float g_U[(size_t)T_DIM * B_DIM * 3 * H_DIM];    // 402 MB

// ---------------------------------------------------------------------------
// Dense1: h[row][j] = sum_k x[row][k]*W1[k][j] + b1[j], row = t*B+b, K=20
// ---------------------------------------------------------------------------
__global__ void dense1_kernel(const float* __restrict__ x,
                              const float* __restrict__ W1,
                              const float* __restrict__ b1,
                              float* __restrict__ h) {
    int row = blockIdx.x;  // 0 .. T*B-1
    __shared__ float xs[DIN];
    if (threadIdx.x < DIN) xs[threadIdx.x] = x[(size_t)row * DIN + threadIdx.x];
    __syncthreads();
    for (int j = threadIdx.x; j < H_DIM; j += blockDim.x) {
        float acc = b1[j];
#pragma unroll
        for (int k = 0; k < DIN; k++) acc += xs[k] * W1[k * H_DIM + j];
        h[(size_t)row * H_DIM + j] = acc;
    }
}

// ---------------------------------------------------------------------------
// SGEMM: C[M,N] = A[M,K] @ B[K,N] (+ bias). Row-major. M%128==0, K%8==0.
// N guarded (for Dense3, N=1095). 128x128x8 tiles, 256 threads, 8x8/thread.
// ---------------------------------------------------------------------------
#define BM 128
#define BN 128
#define BK 8
#define TM 8
#define TN 8

__global__ __launch_bounds__(256, 2) void sgemm_kernel(
    const float* __restrict__ A, const float* __restrict__ Bm,
    float* __restrict__ C, int M, int N, int K,
    const float* __restrict__ bias) {
    __shared__ float As[BK][BM];
    __shared__ float Bs[BK][BN];

    const int tid = threadIdx.x;
    const int rowC0 = blockIdx.y * BM;
    const int colC0 = blockIdx.x * BN;

    // A tile load: float4 along K. 128 rows x 8 cols -> 256 float4 loads.
    const int aRow = tid >> 1;          // 0..127
    const int aCol = (tid & 1) * 4;     // 0 or 4
    // B tile load: 8 rows x 128 cols, 4 scalar (guarded) loads per thread.
    const int bRow = tid >> 5;          // 0..7
    const int bCol0 = (tid & 31) * 4;   // 0,4,...,124

    const int ty = tid >> 4;            // 0..15 -> M micro-tile
    const int tx = tid & 15;            // 0..15 -> N micro-tile

    float acc[TM][TN];
#pragma unroll
    for (int i = 0; i < TM; i++)
#pragma unroll
        for (int j = 0; j < TN; j++) acc[i][j] = 0.0f;

    const float* Aptr = A + (size_t)(rowC0 + aRow) * K + aCol;

    for (int k0 = 0; k0 < K; k0 += BK) {
        float4 av = *(const float4*)(Aptr + k0);
        As[aCol + 0][aRow] = av.x;
        As[aCol + 1][aRow] = av.y;
        As[aCol + 2][aRow] = av.z;
        As[aCol + 3][aRow] = av.w;

        const float* Brow = Bm + (size_t)(k0 + bRow) * N;
#pragma unroll
        for (int j = 0; j < 4; j++) {
            int col = colC0 + bCol0 + j;
            Bs[bRow][bCol0 + j] = (col < N) ? Brow[col] : 0.0f;
        }
        __syncthreads();

#pragma unroll
        for (int k = 0; k < BK; k++) {
            float ra[TM], rb[TN];
#pragma unroll
            for (int i = 0; i < TM; i++) ra[i] = As[k][ty * TM + i];
#pragma unroll
            for (int j = 0; j < TN; j++) rb[j] = Bs[k][tx * TN + j];
#pragma unroll
            for (int i = 0; i < TM; i++)
#pragma unroll
                for (int j = 0; j < TN; j++) acc[i][j] += ra[i] * rb[j];
        }
        __syncthreads();
    }

#pragma unroll
    for (int i = 0; i < TM; i++) {
        int row = rowC0 + ty * TM + i;
#pragma unroll
        for (int j = 0; j < TN; j++) {
            int col = colC0 + tx * TN + j;
            if (col < N) {
                float v = acc[i][j];
                if (bias) v += bias[col];
                C[(size_t)row * N + col] = v;
            }
        }
    }
}

// ---------------------------------------------------------------------------
// SRU scan: one thread per (b,h). Sequential over T. In-place h update
// (read h[t] before writing h[t]; each thread owns its (b,h) slot).
// U row layout per (t,b): [z(0..H) | f_pre(H..2H) | r_pre(2H..3H)]
// ---------------------------------------------------------------------------
__global__ void sru_scan_kernel(const float* __restrict__ U,
                                float* __restrict__ h,
                                const float* __restrict__ bf,
                                const float* __restrict__ br,
                                float* __restrict__ c_out) {
    int idx = blockIdx.x * blockDim.x + threadIdx.x;  // 0..B*H-1
    int b = idx / H_DIM;
    int hh = idx - b * H_DIM;
    float bfv = bf[hh];
    float brv = br[hh];
    float c = 0.0f;

    const size_t rowStrideU = (size_t)3 * H_DIM;
    const float* Ub = U + (size_t)b * rowStrideU + hh;
    float* hb = h + (size_t)b * H_DIM + hh;

    for (int t = 0; t < T_DIM; t++) {
        const float* Ut = Ub + (size_t)t * B_DIM * rowStrideU;
        float z = Ut[0];
        float fp = Ut[H_DIM];
        float rp = Ut[2 * H_DIM];
        float f = 1.0f / (1.0f + __expf(-(fp + bfv)));
        float r = 1.0f / (1.0f + __expf(-(rp + brv)));
        c = f * c + (1.0f - f) * z;
        float* hp = hb + (size_t)t * B_DIM * H_DIM;
        float hin = *hp;
        *hp = r * c + (1.0f - r) * hin;
    }
    c_out[idx] = c;
}

// ---------------------------------------------------------------------------
// Launch
// ---------------------------------------------------------------------------
extern "C" void kernel_launch(void* const* d_in, const int* in_sizes, int n_in,
                              void* d_out, int out_size) {
    const float* x     = (const float*)d_in[0];
    // d_in[1] = c (unused, matches reference)
    const float* W1    = (const float*)d_in[2];
    const float* b1    = (const float*)d_in[3];
    const float* W_sru = (const float*)d_in[4];
    const float* bf    = (const float*)d_in[5];
    const float* br    = (const float*)d_in[6];
    const float* W3    = (const float*)d_in[7];
    const float* b3    = (const float*)d_in[8];
    float* out = (float*)d_out;

    float *h_buf, *U_buf;
    cudaGetSymbolAddress((void**)&h_buf, g_h);
    cudaGetSymbolAddress((void**)&U_buf, g_U);

    const int M = T_DIM * B_DIM;  // 32768

    dense1_kernel<<<M, 256>>>(x, W1, b1, h_buf);

    float* c_base = out + (size_t)M * OUT_DIM;
    for (int l = 0; l < L_DIM; l++) {
        dim3 grid(3 * H_DIM / BN, M / BM);
        sgemm_kernel<<<grid, 256>>>(h_buf, W_sru + (size_t)l * H_DIM * 3 * H_DIM,
                                    U_buf, M, 3 * H_DIM, H_DIM, nullptr);
        sru_scan_kernel<<<(B_DIM * H_DIM) / 256, 256>>>(
            U_buf, h_buf, bf + l * H_DIM, br + l * H_DIM,
            c_base + (size_t)l * B_DIM * H_DIM);
    }

    dim3 grid3((OUT_DIM + BN - 1) / BN, M / BM);
    sgemm_kernel<<<grid3, 256>>>(h_buf, W3, out, M, OUT_DIM, H_DIM, b3);
}

// round 4
// speedup vs baseline: 2.6901x; 2.6901x over previous
#include <cuda_runtime.h>
#include <cstdint>

#define T_DIM 256
#define B_DIM 128
#define DIN 20
#define H_DIM 1024
#define OUT_DIM 1095
#define L_DIM 3

__device__ float g_h[(size_t)T_DIM * B_DIM * H_DIM];        // 134 MB
__device__ float g_U[(size_t)T_DIM * B_DIM * 3 * H_DIM];    // 402 MB

// ---------------------------------------------------------------------------
// Dense1 (K=20, memory-bound)
// ---------------------------------------------------------------------------
__global__ void dense1_kernel(const float* __restrict__ x,
                              const float* __restrict__ W1,
                              const float* __restrict__ b1,
                              float* __restrict__ h) {
    int row = blockIdx.x;
    __shared__ float xs[DIN];
    if (threadIdx.x < DIN) xs[threadIdx.x] = x[(size_t)row * DIN + threadIdx.x];
    __syncthreads();
    for (int j = threadIdx.x; j < H_DIM; j += blockDim.x) {
        float acc = b1[j];
#pragma unroll
        for (int k = 0; k < DIN; k++) acc += xs[k] * W1[k * H_DIM + j];
        h[(size_t)row * H_DIM + j] = acc;
    }
}

// ---------------------------------------------------------------------------
// TF32 tensor-core GEMM: C = A@B (+bias). 128x128x16 block, 8 warps (4Mx2N),
// warp tile 32x64, mma.sync.m16n8k8.tf32.
// A smem: [128][20] padded, scalar LDS fragments (conflict-free, verified).
// B smem: fragment-packed uint2 layout with XOR-by-nt lane swizzle.
// ---------------------------------------------------------------------------
#define GBM 128
#define GBN 128
#define GBK 16
#define SA 20   // A smem row stride (pad 16 -> 20)

__device__ __forceinline__ uint32_t f2tf32(float v) {
    uint32_t u;
    asm("cvt.rna.tf32.f32 %0, %1;" : "=r"(u) : "f"(v));
    return u;
}

template <bool VEC_B>
__global__ __launch_bounds__(256) void tf32_gemm(
    const float* __restrict__ A, const float* __restrict__ Bm,
    float* __restrict__ C, int M, int N, int K,
    const float* __restrict__ bias) {
    __shared__ uint32_t As[GBM * SA];          // 10240 B
    // Bs word index: ((kk*16 + nt)*32 + (lane ^ nt))*2 + jj
    // logical lane = n*4 + kq ; jj: 0 -> B[kk*8+kq][nt*8+n], 1 -> k+4
    __shared__ uint32_t Bs[2 * 16 * 32 * 2];   // 8192 B

    const int tid = threadIdx.x;
    const int lane = tid & 31;
    const int warp = tid >> 5;
    const int wm = warp >> 1;   // 0..3
    const int wn = warp & 1;    // 0..1
    const int rowC0 = blockIdx.y * GBM;
    const int colC0 = blockIdx.x * GBN;

    // A loader: thread -> (row = tid>>1, kHalf = tid&1), 2 float4 along K
    const int aRow = tid >> 1;
    const int aKk = tid & 1;
    const float* Ag = A + (size_t)(rowC0 + aRow) * K + aKk * 8;

    // B loader: i=0,1 -> k = i*8 + warp ; n = lane*4 + q
    const int bNt = lane >> 1;                  // nt = (lane*4+q)>>3 for all q
    const int bHalf = lane & 1;
    const int bW3 = warp & 3;                   // kq within k4-half
    const int bJj = (warp >> 2) & 1;            // which k4-half
    const int bCol0 = colC0 + lane * 4;
    const float* Bg = Bm + (size_t)warp * N + bCol0;

    float acc[2][8][4];
#pragma unroll
    for (int mi = 0; mi < 2; mi++)
#pragma unroll
        for (int ni = 0; ni < 8; ni++)
#pragma unroll
            for (int j = 0; j < 4; j++) acc[mi][ni][j] = 0.0f;

    const int ntiles = K / GBK;

    float4 ra[2], rb[2];

    // prologue loads (tile 0)
#pragma unroll
    for (int f = 0; f < 2; f++) ra[f] = *(const float4*)(Ag + f * 4);
#pragma unroll
    for (int i = 0; i < 2; i++) {
        const float* p = Bg + (size_t)i * 8 * N;
        if (VEC_B) {
            rb[i] = *(const float4*)p;
        } else {
            rb[i].x = (bCol0 + 0 < N) ? p[0] : 0.0f;
            rb[i].y = (bCol0 + 1 < N) ? p[1] : 0.0f;
            rb[i].z = (bCol0 + 2 < N) ? p[2] : 0.0f;
            rb[i].w = (bCol0 + 3 < N) ? p[3] : 0.0f;
        }
    }

    for (int t = 0; t < ntiles; t++) {
        // ---- A stores: [row][k], STS.128, converted to tf32
#pragma unroll
        for (int f = 0; f < 2; f++) {
            uint4 w;
            w.x = f2tf32(ra[f].x); w.y = f2tf32(ra[f].y);
            w.z = f2tf32(ra[f].z); w.w = f2tf32(ra[f].w);
            *(uint4*)&As[aRow * SA + aKk * 8 + f * 4] = w;
        }
        // ---- B stores: fragment-packed + XOR swizzle (2-way max)
        {
            float v[2][4] = {{rb[0].x, rb[0].y, rb[0].z, rb[0].w},
                             {rb[1].x, rb[1].y, rb[1].z, rb[1].w}};
#pragma unroll
            for (int i = 0; i < 2; i++)
#pragma unroll
                for (int q = 0; q < 4; q++) {
                    int laneL = 16 * bHalf + 4 * q + bW3;   // logical n*4+kq
                    int phys = laneL ^ bNt;
                    Bs[((i * 16 + bNt) * 32 + phys) * 2 + bJj] = f2tf32(v[i][q]);
                }
        }
        __syncthreads();

        // ---- prefetch next tile
        if (t + 1 < ntiles) {
            const float* Agn = Ag + (t + 1) * GBK;
#pragma unroll
            for (int f = 0; f < 2; f++) ra[f] = *(const float4*)(Agn + f * 4);
            const float* Bgn = Bg + (size_t)(t + 1) * GBK * N;
#pragma unroll
            for (int i = 0; i < 2; i++) {
                const float* p = Bgn + (size_t)i * 8 * N;
                if (VEC_B) {
                    rb[i] = *(const float4*)p;
                } else {
                    rb[i].x = (bCol0 + 0 < N) ? p[0] : 0.0f;
                    rb[i].y = (bCol0 + 1 < N) ? p[1] : 0.0f;
                    rb[i].z = (bCol0 + 2 < N) ? p[2] : 0.0f;
                    rb[i].w = (bCol0 + 3 < N) ? p[3] : 0.0f;
                }
            }
        }

        // ---- compute: 2 k8-steps x (2 mi x 8 ni) MMAs
        const int gr = lane >> 2;   // groupID (m row within 8 / n col)
        const int gc = lane & 3;    // threadID in group (k col)
#pragma unroll
        for (int kk = 0; kk < 2; kk++) {
            uint4 af[2];
#pragma unroll
            for (int mi = 0; mi < 2; mi++) {
                int base = (wm * 32 + mi * 16 + gr) * SA + kk * 8 + gc;
                af[mi].x = As[base];
                af[mi].y = As[base + 8 * SA];
                af[mi].z = As[base + 4];
                af[mi].w = As[base + 8 * SA + 4];
            }
            uint2 bf[8];
#pragma unroll
            for (int ni = 0; ni < 8; ni++) {
                int nt = wn * 8 + ni;
                bf[ni] = *(const uint2*)&Bs[((kk * 16 + nt) * 32 + (lane ^ nt)) * 2];
            }
#pragma unroll
            for (int mi = 0; mi < 2; mi++)
#pragma unroll
                for (int ni = 0; ni < 8; ni++) {
                    asm volatile(
                        "mma.sync.aligned.m16n8k8.row.col.f32.tf32.tf32.f32 "
                        "{%0,%1,%2,%3}, {%4,%5,%6,%7}, {%8,%9}, {%0,%1,%2,%3};\n"
                        : "+f"(acc[mi][ni][0]), "+f"(acc[mi][ni][1]),
                          "+f"(acc[mi][ni][2]), "+f"(acc[mi][ni][3])
                        : "r"(af[mi].x), "r"(af[mi].y), "r"(af[mi].z), "r"(af[mi].w),
                          "r"(bf[ni].x), "r"(bf[ni].y));
                }
        }
        __syncthreads();
    }

    // ---- epilogue (standard m16n8 C fragment layout)
    const int gr = lane >> 2;
    const int gc = (lane & 3) * 2;
#pragma unroll
    for (int mi = 0; mi < 2; mi++) {
        int r0 = rowC0 + wm * 32 + mi * 16 + gr;
#pragma unroll
        for (int ni = 0; ni < 8; ni++) {
            int c0 = colC0 + wn * 64 + ni * 8 + gc;
            float b0 = 0.0f, b1 = 0.0f;
            if (bias) {
                if (c0 < N) b0 = bias[c0];
                if (c0 + 1 < N) b1 = bias[c0 + 1];
            }
            float* Cp0 = C + (size_t)r0 * N + c0;
            float* Cp1 = C + (size_t)(r0 + 8) * N + c0;
            if (c0 < N) {
                Cp0[0] = acc[mi][ni][0] + b0;
                Cp1[0] = acc[mi][ni][2] + b0;
            }
            if (c0 + 1 < N) {
                Cp0[1] = acc[mi][ni][1] + b1;
                Cp1[1] = acc[mi][ni][3] + b1;
            }
        }
    }
}

// ---------------------------------------------------------------------------
// SRU scan: one thread per (b,h). Sequential over T. In-place h update.
// ---------------------------------------------------------------------------
__global__ void sru_scan_kernel(const float* __restrict__ U,
                                float* __restrict__ h,
                                const float* __restrict__ bf,
                                const float* __restrict__ br,
                                float* __restrict__ c_out) {
    int idx = blockIdx.x * blockDim.x + threadIdx.x;
    int b = idx / H_DIM;
    int hh = idx - b * H_DIM;
    float bfv = bf[hh];
    float brv = br[hh];
    float c = 0.0f;

    const size_t rowStrideU = (size_t)3 * H_DIM;
    const float* Ub = U + (size_t)b * rowStrideU + hh;
    float* hb = h + (size_t)b * H_DIM + hh;

    for (int t = 0; t < T_DIM; t++) {
        const float* Ut = Ub + (size_t)t * B_DIM * rowStrideU;
        float z = Ut[0];
        float fp = Ut[H_DIM];
        float rp = Ut[2 * H_DIM];
        float f = 1.0f / (1.0f + __expf(-(fp + bfv)));
        float r = 1.0f / (1.0f + __expf(-(rp + brv)));
        c = f * c + (1.0f - f) * z;
        float* hp = hb + (size_t)t * B_DIM * H_DIM;
        float hin = *hp;
        *hp = r * c + (1.0f - r) * hin;
    }
    c_out[idx] = c;
}

// ---------------------------------------------------------------------------
// Launch
// ---------------------------------------------------------------------------
extern "C" void kernel_launch(void* const* d_in, const int* in_sizes, int n_in,
                              void* d_out, int out_size) {
    const float* x     = (const float*)d_in[0];
    const float* W1    = (const float*)d_in[2];
    const float* b1    = (const float*)d_in[3];
    const float* W_sru = (const float*)d_in[4];
    const float* bf    = (const float*)d_in[5];
    const float* br    = (const float*)d_in[6];
    const float* W3    = (const float*)d_in[7];
    const float* b3    = (const float*)d_in[8];
    float* out = (float*)d_out;

    float *h_buf, *U_buf;
    cudaGetSymbolAddress((void**)&h_buf, g_h);
    cudaGetSymbolAddress((void**)&U_buf, g_U);

    const int M = T_DIM * B_DIM;  // 32768

    dense1_kernel<<<M, 256>>>(x, W1, b1, h_buf);

    float* c_base = out + (size_t)M * OUT_DIM;
    for (int l = 0; l < L_DIM; l++) {
        dim3 grid(3 * H_DIM / GBN, M / GBM);
        tf32_gemm<true><<<grid, 256>>>(h_buf, W_sru + (size_t)l * H_DIM * 3 * H_DIM,
                                       U_buf, M, 3 * H_DIM, H_DIM, nullptr);
        sru_scan_kernel<<<(B_DIM * H_DIM) / 256, 256>>>(
            U_buf, h_buf, bf + l * H_DIM, br + l * H_DIM,
            c_base + (size_t)l * B_DIM * H_DIM);
    }

    dim3 grid3((OUT_DIM + GBN - 1) / GBN, M / GBM);
    tf32_gemm<false><<<grid3, 256>>>(h_buf, W3, out, M, OUT_DIM, H_DIM, b3);
}

// round 6
// speedup vs baseline: 2.9766x; 1.1065x over previous
#include <cuda_runtime.h>
#include <cstdint>

#define T_DIM 256
#define B_DIM 128
#define DIN 20
#define H_DIM 1024
#define OUT_DIM 1095
#define L_DIM 3
#define M_ALL (T_DIM * B_DIM)   // 32768
#define N_SRU (3 * H_DIM)       // 3072
#define N3PAD 1152              // OUT padded to 128

// ---------------- scratch ----------------
__device__ float g_h[(size_t)M_ALL * H_DIM];                 // 134 MB (tf32-rounded values)
__device__ float g_U[(size_t)M_ALL * N_SRU];                 // 402 MB
__device__ float g_WT[(size_t)L_DIM * N_SRU * H_DIM];        // 37.7 MB ([N][K] tf32)
__device__ float g_W3T[(size_t)N3PAD * H_DIM];               // 4.7 MB

__device__ __forceinline__ uint32_t f2tf32(float v) {
    uint32_t u;
    asm("cvt.rna.tf32.f32 %0, %1;" : "=r"(u) : "f"(v));
    return u;
}
__device__ __forceinline__ float f2tf32f(float v) { return __uint_as_float(f2tf32(v)); }

__device__ __forceinline__ uint32_t smem_u32(const void* p) {
    uint32_t a;
    asm("{ .reg .u64 t; cvta.to.shared.u64 t, %1; cvt.u32.u64 %0, t; }" : "=r"(a) : "l"(p));
    return a;
}
__device__ __forceinline__ void cpa16(uint32_t dst, const void* src) {
    asm volatile("cp.async.cg.shared.global [%0], [%1], 16;" :: "r"(dst), "l"(src) : "memory");
}
#define CPA_COMMIT() asm volatile("cp.async.commit_group;" ::: "memory")
#define CPA_WAIT1() asm volatile("cp.async.wait_group 1;" ::: "memory")

__device__ __forceinline__ void ldsm4(uint32_t& r0, uint32_t& r1, uint32_t& r2, uint32_t& r3,
                                      uint32_t addr) {
    asm volatile("ldmatrix.sync.aligned.m8n8.x4.shared.b16 {%0,%1,%2,%3}, [%4];"
                 : "=r"(r0), "=r"(r1), "=r"(r2), "=r"(r3) : "r"(addr));
}

// ---------------------------------------------------------------------------
// Prep: WT[n][k] = tf32(W[k][n]) for n < N else 0.  (K=1024 fixed)
// ---------------------------------------------------------------------------
__global__ void wtransT_kernel(const float* __restrict__ W, float* __restrict__ WT,
                               int N, int Npad) {
    __shared__ float tile[32][33];
    int n0 = blockIdx.x * 32, k0 = blockIdx.y * 32;
#pragma unroll
    for (int i = 0; i < 4; i++) {
        int k = k0 + threadIdx.y + i * 8;
        int n = n0 + threadIdx.x;
        tile[threadIdx.y + i * 8][threadIdx.x] = (n < N) ? W[(size_t)k * N + n] : 0.0f;
    }
    __syncthreads();
#pragma unroll
    for (int i = 0; i < 4; i++) {
        int n = n0 + threadIdx.y + i * 8;
        if (n < Npad)
            WT[(size_t)n * H_DIM + k0 + threadIdx.x] = f2tf32f(tile[threadIdx.x][threadIdx.y + i * 8]);
    }
}

// ---------------------------------------------------------------------------
// Dense1: h = tf32_round(x@W1 + b1)
// ---------------------------------------------------------------------------
__global__ void dense1_kernel(const float* __restrict__ x,
                              const float* __restrict__ W1,
                              const float* __restrict__ b1,
                              float* __restrict__ h) {
    int row = blockIdx.x;
    __shared__ float xs[DIN];
    if (threadIdx.x < DIN) xs[threadIdx.x] = x[(size_t)row * DIN + threadIdx.x];
    __syncthreads();
    for (int j = threadIdx.x; j < H_DIM; j += blockDim.x) {
        float acc = b1[j];
#pragma unroll
        for (int k = 0; k < DIN; k++) acc += xs[k] * W1[k * H_DIM + j];
        h[(size_t)row * H_DIM + j] = f2tf32f(acc);
    }
}

// ---------------------------------------------------------------------------
// TF32 GEMM: C[M,N] = A[M,1024] @ BT[N,1024]^T (+bias)
// CTA 128x128, 8 warps (4M x 2N), warp 32x64. BK=32, 3-stage cp.async.
// smem per stage: A 128x128B + B 128x128B, chunk-XOR swizzled.
// Fragments via ldmatrix.x4 (conflict-free).
// ---------------------------------------------------------------------------
#define BK32 32
#define STAGE_B (128 * 128)             // bytes for one operand tile
#define STAGE_SZ (2 * STAGE_B)          // 32 KB
#define NSTAGES 3
#define NTILES (H_DIM / BK32)           // 32

template <bool GUARD_N>
__global__ __launch_bounds__(256) void tf32_gemm(
    const float* __restrict__ A, const float* __restrict__ BT,
    float* __restrict__ C, int ldC, int Nvalid, const float* __restrict__ bias) {
    extern __shared__ char smem[];
    const uint32_t sbase = smem_u32(smem);
    const int tid = threadIdx.x;
    const int lane = tid & 31;
    const int warp = tid >> 5;
    const int wm = warp >> 1;           // 0..3 (m)
    const int wn = warp & 1;            // 0..1 (n)

    // cp.async writer mapping: r = tid>>1 (row 0..127), 4 chunks c = (tid&1)*4 + j
    const int ldR = tid >> 1;
    const int ldC0 = (tid & 1) * 4;
    const float* Ag = A + ((size_t)blockIdx.y * 128 + ldR) * H_DIM + ldC0 * 4;
    const float* Bg = BT + ((size_t)blockIdx.x * 128 + ldR) * H_DIM + ldC0 * 4;

    // ldmatrix per-lane constants
    const int mat = lane >> 3;          // 0..3
    const int mrow = lane & 7;
    const int rowInMat = 8 * (mat & 1) + mrow;
    const int matHalf = mat >> 1;       // chunk offset within k8

    float acc[2][8][4];
#pragma unroll
    for (int mi = 0; mi < 2; mi++)
#pragma unroll
        for (int ni = 0; ni < 8; ni++)
#pragma unroll
            for (int j = 0; j < 4; j++) acc[mi][ni][j] = 0.0f;

    // ---- pipeline
    auto issue_stage = [&](int t) {
        if (t < NTILES) {
            uint32_t st = sbase + (uint32_t)(t % NSTAGES) * STAGE_SZ;
            const float* a = Ag + t * BK32;
            const float* b = Bg + t * BK32;
#pragma unroll
            for (int j = 0; j < 4; j++) {
                int c = ldC0 + j;
                uint32_t off = (uint32_t)ldR * 128 + (uint32_t)((c ^ (ldR & 7)) << 4);
                cpa16(st + off, a + j * 4);
                cpa16(st + STAGE_B + off, b + j * 4);
            }
        }
        CPA_COMMIT();
    };

    issue_stage(0);
    issue_stage(1);

    for (int t = 0; t < NTILES; t++) {
        CPA_WAIT1();
        __syncthreads();
        const uint32_t stA = sbase + (uint32_t)(t % NSTAGES) * STAGE_SZ;
        const uint32_t stB = stA + STAGE_B;

#pragma unroll
        for (int kk = 0; kk < 4; kk++) {
            const int chunk = kk * 2 + matHalf;
            const uint32_t swoff = (uint32_t)((chunk ^ mrow) << 4);
            // A fragments: 2 x ldmatrix.x4 (m16 each)
            uint4 af[2];
#pragma unroll
            for (int mi = 0; mi < 2; mi++) {
                int row = wm * 32 + mi * 16 + rowInMat;
                ldsm4(af[mi].x, af[mi].y, af[mi].z, af[mi].w,
                      stA + (uint32_t)row * 128 + swoff);
            }
            // B fragments: 4 x ldmatrix.x4 (n16 each)
            uint4 bf4[4];
#pragma unroll
            for (int g = 0; g < 4; g++) {
                int row = wn * 64 + g * 16 + rowInMat;
                ldsm4(bf4[g].x, bf4[g].y, bf4[g].z, bf4[g].w,
                      stB + (uint32_t)row * 128 + swoff);
            }
#pragma unroll
            for (int mi = 0; mi < 2; mi++)
#pragma unroll
                for (int g = 0; g < 4; g++) {
                    asm volatile(
                        "mma.sync.aligned.m16n8k8.row.col.f32.tf32.tf32.f32 "
                        "{%0,%1,%2,%3}, {%4,%5,%6,%7}, {%8,%9}, {%0,%1,%2,%3};\n"
                        : "+f"(acc[mi][2 * g][0]), "+f"(acc[mi][2 * g][1]),
                          "+f"(acc[mi][2 * g][2]), "+f"(acc[mi][2 * g][3])
                        : "r"(af[mi].x), "r"(af[mi].y), "r"(af[mi].z), "r"(af[mi].w),
                          "r"(bf4[g].x), "r"(bf4[g].z));
                    asm volatile(
                        "mma.sync.aligned.m16n8k8.row.col.f32.tf32.tf32.f32 "
                        "{%0,%1,%2,%3}, {%4,%5,%6,%7}, {%8,%9}, {%0,%1,%2,%3};\n"
                        : "+f"(acc[mi][2 * g + 1][0]), "+f"(acc[mi][2 * g + 1][1]),
                          "+f"(acc[mi][2 * g + 1][2]), "+f"(acc[mi][2 * g + 1][3])
                        : "r"(af[mi].x), "r"(af[mi].y), "r"(af[mi].z), "r"(af[mi].w),
                          "r"(bf4[g].y), "r"(bf4[g].w));
                }
        }
        __syncthreads();
        issue_stage(t + 2);
    }

    // ---- epilogue
    const int gr = lane >> 2;
    const int gc = (lane & 3) * 2;
#pragma unroll
    for (int mi = 0; mi < 2; mi++) {
        int r0 = blockIdx.y * 128 + wm * 32 + mi * 16 + gr;
#pragma unroll
        for (int ni = 0; ni < 8; ni++) {
            int c0 = blockIdx.x * 128 + wn * 64 + ni * 8 + gc;
            float b0 = 0.0f, b1 = 0.0f;
            if (bias) {
                if (!GUARD_N || c0 < Nvalid) b0 = bias[c0];
                if (!GUARD_N || c0 + 1 < Nvalid) b1 = bias[c0 + 1];
            }
            float* Cp0 = C + (size_t)r0 * ldC + c0;
            float* Cp1 = C + (size_t)(r0 + 8) * ldC + c0;
            if (!GUARD_N || c0 < Nvalid) {
                Cp0[0] = acc[mi][ni][0] + b0;
                Cp1[0] = acc[mi][ni][2] + b0;
            }
            if (!GUARD_N || c0 + 1 < Nvalid) {
                Cp0[1] = acc[mi][ni][1] + b1;
                Cp1[1] = acc[mi][ni][3] + b1;
            }
        }
    }
}

// ---------------------------------------------------------------------------
// SRU scan: one thread per (b,h). In-place h update (tf32-rounded writes).
// ---------------------------------------------------------------------------
__global__ void sru_scan_kernel(const float* __restrict__ U,
                                float* __restrict__ h,
                                const float* __restrict__ bf,
                                const float* __restrict__ br,
                                float* __restrict__ c_out) {
    int idx = blockIdx.x * blockDim.x + threadIdx.x;
    int b = idx / H_DIM;
    int hh = idx - b * H_DIM;
    float bfv = bf[hh];
    float brv = br[hh];
    float c = 0.0f;

    const float* Ub = U + (size_t)b * N_SRU + hh;
    float* hb = h + (size_t)b * H_DIM + hh;

    for (int t = 0; t < T_DIM; t++) {
        const float* Ut = Ub + (size_t)t * B_DIM * N_SRU;
        float z = Ut[0];
        float fp = Ut[H_DIM];
        float rp = Ut[2 * H_DIM];
        float f = 1.0f / (1.0f + __expf(-(fp + bfv)));
        float r = 1.0f / (1.0f + __expf(-(rp + brv)));
        c = f * c + (1.0f - f) * z;
        float* hp = hb + (size_t)t * B_DIM * H_DIM;
        float hin = *hp;
        *hp = f2tf32f(r * c + (1.0f - r) * hin);
    }
    c_out[idx] = c;
}

// ---------------------------------------------------------------------------
// Launch
// ---------------------------------------------------------------------------
extern "C" void kernel_launch(void* const* d_in, const int* in_sizes, int n_in,
                              void* d_out, int out_size) {
    const float* x     = (const float*)d_in[0];
    const float* W1    = (const float*)d_in[2];
    const float* b1    = (const float*)d_in[3];
    const float* W_sru = (const float*)d_in[4];
    const float* bf    = (const float*)d_in[5];
    const float* br    = (const float*)d_in[6];
    const float* W3    = (const float*)d_in[7];
    const float* b3    = (const float*)d_in[8];
    float* out = (float*)d_out;

    float *h_buf, *U_buf, *WT, *W3T;
    cudaGetSymbolAddress((void**)&h_buf, g_h);
    cudaGetSymbolAddress((void**)&U_buf, g_U);
    cudaGetSymbolAddress((void**)&WT, g_WT);
    cudaGetSymbolAddress((void**)&W3T, g_W3T);

    const int smemSz = NSTAGES * STAGE_SZ;   // 96 KB
    cudaFuncSetAttribute(tf32_gemm<false>, cudaFuncAttributeMaxDynamicSharedMemorySize, smemSz);
    cudaFuncSetAttribute(tf32_gemm<true>, cudaFuncAttributeMaxDynamicSharedMemorySize, smemSz);

    // prep: W transposes (tf32-rounded)
    {
        dim3 blk(32, 8);
        for (int l = 0; l < L_DIM; l++) {
            dim3 grd(N_SRU / 32, H_DIM / 32);
            wtransT_kernel<<<grd, blk>>>(W_sru + (size_t)l * H_DIM * N_SRU,
                                         WT + (size_t)l * N_SRU * H_DIM, N_SRU, N_SRU);
        }
        dim3 grd3(N3PAD / 32, H_DIM / 32);
        wtransT_kernel<<<grd3, blk>>>(W3, W3T, OUT_DIM, N3PAD);
    }

    dense1_kernel<<<M_ALL, 256>>>(x, W1, b1, h_buf);

    float* c_base = out + (size_t)M_ALL * OUT_DIM;
    for (int l = 0; l < L_DIM; l++) {
        dim3 grid(N_SRU / 128, M_ALL / 128);
        tf32_gemm<false><<<grid, 256, smemSz>>>(
            h_buf, WT + (size_t)l * N_SRU * H_DIM, U_buf, N_SRU, N_SRU, nullptr);
        sru_scan_kernel<<<(B_DIM * H_DIM) / 256, 256>>>(
            U_buf, h_buf, bf + l * H_DIM, br + l * H_DIM,
            c_base + (size_t)l * B_DIM * H_DIM);
    }

    dim3 grid3(N3PAD / 128, M_ALL / 128);
    tf32_gemm<true><<<grid3, 256, smemSz>>>(h_buf, W3T, out, OUT_DIM, OUT_DIM, b3);
}